// round 4
// baseline (speedup 1.0000x reference)
#include <cuda_runtime.h>
#include <cstdint>

#define B_ 32
#define D_ 128
#define T_ 2250
#define Q_ 32
#define K_ 1024
#define N_ (B_*T_)          // 72000
#define NBLK 563            // ceil(N/128)

// Residual scratch [N][D] and per-code squared norms [Q][K].
__device__ __align__(16) float g_resid[(size_t)N_ * D_];
__device__ __align__(16) float g_cnorm[Q_ * K_];

// ---------------------------------------------------------------------------
// Transpose embeddings [B, D, T] -> g_resid [(b*T + t), d]
// ---------------------------------------------------------------------------
__global__ void transpose_kernel(const float* __restrict__ in)
{
    __shared__ float tile[32][33];
    const int b  = blockIdx.z;
    const int t0 = blockIdx.x * 32;
    const int d0 = blockIdx.y * 32;
    const int tx = threadIdx.x;     // 0..31
    const int ty = threadIdx.y;     // 0..7

    #pragma unroll
    for (int k = 0; k < 4; k++) {
        int d = d0 + ty + k * 8;
        int t = t0 + tx;
        float v = 0.0f;
        if (t < T_) v = in[((size_t)b * D_ + d) * T_ + t];
        tile[ty + k * 8][tx] = v;   // tile[d_local][t_local]
    }
    __syncthreads();
    #pragma unroll
    for (int k = 0; k < 4; k++) {
        int t = t0 + ty + k * 8;
        int d = d0 + tx;
        if (t < T_) g_resid[((size_t)b * T_ + t) * D_ + d] = tile[tx][ty + k * 8];
    }
}

// ---------------------------------------------------------------------------
// Per-code squared norms: one warp per code (Q*K = 32768 codes)
// ---------------------------------------------------------------------------
__global__ void cnorm_kernel(const float* __restrict__ embed)
{
    const int wid  = threadIdx.x >> 5;
    const int lane = threadIdx.x & 31;
    const int code = blockIdx.x * 8 + wid;          // < 32768
    float s = 0.0f;
    #pragma unroll
    for (int j = 0; j < 4; j++) {
        float v = embed[(size_t)code * D_ + lane + 32 * j];
        s = fmaf(v, v, s);
    }
    #pragma unroll
    for (int d = 16; d; d >>= 1) s += __shfl_xor_sync(0xffffffffu, s, d);
    if (lane == 0) g_cnorm[code] = s;
}

// ---------------------------------------------------------------------------
// One RVQ layer. Block = 256 threads, 128 points.
// K in 16 chunks of 64 codes; D in 2 phases of 64. 48KB dynamic smem.
// Micro-tile per thread: 8 points x 4 codes, plain FFMA.
// ---------------------------------------------------------------------------
__global__ void __launch_bounds__(256, 2)
rvq_layer_kernel(const float* __restrict__ embed_all, int q, float* __restrict__ out)
{
    extern __shared__ float4 smem4[];
    float4* r4s  = smem4;               // 2048 float4 (32 KB)
    float4* e4s  = smem4 + 2048;        // 1024 float4 (16 KB)
    int*    sidx = (int*)(smem4 + 2048);  // aliases e4s, used after main loop

    const int tid = threadIdx.x;
    const int tx  = tid & 15;           // code group (4 codes)
    const int ty  = tid >> 4;           // point group (8 points)
    const int blockStart = blockIdx.x * 128;

    const float4* eq = (const float4*)(embed_all + (size_t)q * (K_ * D_));
    float4* rg = (float4*)g_resid;

    float best[8];
    int   bidx[8];
    #pragma unroll
    for (int j = 0; j < 8; j++) { best[j] = -3.4e38f; bidx[j] = 0; }

    for (int chunk = 0; chunk < 16; ++chunk) {
        float acc[8][4];
        #pragma unroll
        for (int a = 0; a < 8; a++)
            #pragma unroll
            for (int c = 0; c < 4; c++) acc[a][c] = 0.0f;

        for (int ph = 0; ph < 2; ++ph) {
            __syncthreads();   // previous phase/chunk readers done
            // ---- load residual half-tile: 8 float4 per thread ----
            #pragma unroll
            for (int i = 0; i < 8; i++) {
                int f   = tid + 256 * i;
                int row = f >> 4;          // 0..127
                int s0  = f & 15;
                int n   = blockStart + row;
                if (n >= N_) n = 0;        // safe dummy for tail block
                r4s[row * 16 + (s0 ^ ((row >> 2) & 15))] =
                    rg[(size_t)n * 32 + ph * 16 + s0];
            }
            // ---- load code half-tile: 4 float4 per thread ----
            #pragma unroll
            for (int i = 0; i < 4; i++) {
                int f   = tid + 256 * i;
                int row = f >> 4;          // 0..63
                int s0  = f & 15;
                e4s[row * 16 + (s0 ^ ((row >> 2) & 15))] =
                    eq[(size_t)(chunk * 64 + row) * 32 + ph * 16 + s0];
            }
            __syncthreads();

            // ---- 128 x 64 x 64d micro-GEMM ----
            #pragma unroll 2
            for (int d4 = 0; d4 < 16; ++d4) {
                float4 ra[8], eb[4];
                #pragma unroll
                for (int j = 0; j < 8; j++) {
                    int row = ty * 8 + j;
                    ra[j] = r4s[row * 16 + (d4 ^ ((row >> 2) & 15))];
                }
                #pragma unroll
                for (int j = 0; j < 4; j++) {
                    eb[j] = e4s[(tx * 4 + j) * 16 + (d4 ^ tx)];
                }
                #pragma unroll
                for (int jp = 0; jp < 8; jp++) {
                    #pragma unroll
                    for (int jc = 0; jc < 4; jc++) {
                        acc[jp][jc] = fmaf(ra[jp].x, eb[jc].x, acc[jp][jc]);
                        acc[jp][jc] = fmaf(ra[jp].y, eb[jc].y, acc[jp][jc]);
                        acc[jp][jc] = fmaf(ra[jp].z, eb[jc].z, acc[jp][jc]);
                        acc[jp][jc] = fmaf(ra[jp].w, eb[jc].w, acc[jp][jc]);
                    }
                }
            }
        }

        // ---- epilogue: score = 2*dot - |e|^2, running argmax (first-max) ----
        float cnv[4];
        #pragma unroll
        for (int jc = 0; jc < 4; jc++)
            cnv[jc] = g_cnorm[q * K_ + chunk * 64 + tx * 4 + jc];
        #pragma unroll
        for (int jp = 0; jp < 8; jp++) {
            #pragma unroll
            for (int jc = 0; jc < 4; jc++) {
                const float s = 2.0f * acc[jp][jc] - cnv[jc];
                const int cg = chunk * 64 + tx * 4 + jc;   // ascending order
                if (s > best[jp]) { best[jp] = s; bidx[jp] = cg; }
            }
        }
    }

    __syncthreads();   // everyone done reading e4s before sidx overwrites it

    // ---- reduce argmax across the 16 tx-lanes sharing each point ----
    #pragma unroll
    for (int jp = 0; jp < 8; jp++) {
        float v  = best[jp];
        int   ix = bidx[jp];
        #pragma unroll
        for (int delta = 1; delta < 16; delta <<= 1) {
            float ov = __shfl_xor_sync(0xffffffffu, v, delta);
            int   oi = __shfl_xor_sync(0xffffffffu, ix, delta);
            if (ov > v || (ov == v && oi < ix)) { v = ov; ix = oi; }
        }
        if (tx == 0) sidx[ty * 8 + jp] = ix;
    }
    __syncthreads();

    // ---- write indices AS FLOAT (output dtype hypothesis: float32) ----
    if (tid < 128) {
        int n = blockStart + tid;
        if (n < N_) out[(size_t)q * N_ + n] = (float)sidx[tid];
    }

    // ---- residual update: r -= e[best] (re-read r from global) ----
    #pragma unroll
    for (int i = 0; i < 16; i++) {
        int f  = tid + 256 * i;
        int p  = f >> 5;          // 0..127
        int d4 = f & 31;          // 0..31
        int n  = blockStart + p;
        if (n < N_) {
            float4 r = rg[(size_t)n * 32 + d4];
            float4 e = eq[(size_t)sidx[p] * 32 + d4];
            float4 w;
            w.x = r.x - e.x; w.y = r.y - e.y; w.z = r.z - e.z; w.w = r.w - e.w;
            rg[(size_t)n * 32 + d4] = w;
        }
    }
}

// ---------------------------------------------------------------------------
extern "C" void kernel_launch(void* const* d_in, const int* in_sizes, int n_in,
                              void* d_out, int out_size)
{
    const float* embeddings = (const float*)d_in[0];
    const float* embed      = (const float*)d_in[1];
    // Identify inputs by element count in case of ordering surprises.
    if (n_in >= 2 && in_sizes[0] == Q_ * K_ * D_ && in_sizes[1] == B_ * D_ * T_) {
        const float* t = embeddings; embeddings = embed; embed = t;
    }
    float* out = (float*)d_out;

    const int smem_bytes = 49152;   // exactly 48KB: no opt-in attribute needed

    // Build residual from embeddings (permute B,D,T -> N,D)
    transpose_kernel<<<dim3(71, 4, 32), dim3(32, 8)>>>(embeddings);
    // Precompute |e|^2 for all Q*K codes
    cnorm_kernel<<<4096, 256>>>(embed);
    // Sequential RVQ layers (hard dependency through the residual)
    for (int q = 0; q < Q_; q++) {
        rvq_layer_kernel<<<NBLK, 256, smem_bytes>>>(embed, q, out);
    }
}

// round 5
// speedup vs baseline: 1.0840x; 1.0840x over previous
#include <cuda_runtime.h>
#include <cstdint>

#define B_ 32
#define D_ 128
#define T_ 2250
#define Q_ 32
#define K_ 1024
#define N_ (B_*T_)          // 72000
#define NBLK 563            // ceil(N/128)

// Residual scratch [N][D] and per-code squared norms [Q][K].
__device__ __align__(16) float g_resid[(size_t)N_ * D_];
__device__ __align__(16) float g_cnorm[Q_ * K_];

// ---------------------------------------------------------------------------
__global__ void transpose_kernel(const float* __restrict__ in)
{
    __shared__ float tile[32][33];
    const int b  = blockIdx.z;
    const int t0 = blockIdx.x * 32;
    const int d0 = blockIdx.y * 32;
    const int tx = threadIdx.x;
    const int ty = threadIdx.y;

    #pragma unroll
    for (int k = 0; k < 4; k++) {
        int d = d0 + ty + k * 8;
        int t = t0 + tx;
        float v = 0.0f;
        if (t < T_) v = in[((size_t)b * D_ + d) * T_ + t];
        tile[ty + k * 8][tx] = v;
    }
    __syncthreads();
    #pragma unroll
    for (int k = 0; k < 4; k++) {
        int t = t0 + ty + k * 8;
        int d = d0 + tx;
        if (t < T_) g_resid[((size_t)b * T_ + t) * D_ + d] = tile[tx][ty + k * 8];
    }
}

// ---------------------------------------------------------------------------
__global__ void cnorm_kernel(const float* __restrict__ embed)
{
    const int wid  = threadIdx.x >> 5;
    const int lane = threadIdx.x & 31;
    const int code = blockIdx.x * 8 + wid;
    float s = 0.0f;
    #pragma unroll
    for (int j = 0; j < 4; j++) {
        float v = embed[(size_t)code * D_ + lane + 32 * j];
        s = fmaf(v, v, s);
    }
    #pragma unroll
    for (int d = 16; d; d >>= 1) s += __shfl_xor_sync(0xffffffffu, s, d);
    if (lane == 0) g_cnorm[code] = s;
}

// ---------------------------------------------------------------------------
// Packed dual-FMA: acc.(lo,hi) += a.(lo,hi) * b.(lo,hi)   (sm_100+ f32x2)
__device__ __forceinline__ void ffma2(unsigned long long& acc,
                                      unsigned long long a,
                                      unsigned long long b)
{
    asm("fma.rn.f32x2 %0, %1, %2, %0;" : "+l"(acc) : "l"(a), "l"(b));
}

// ---------------------------------------------------------------------------
// One RVQ layer. Block = 256 threads (tx=tid&7, ty=tid>>3), 128 points.
// K in 32 chunks of 32 codes, full D=128 resident in smem.
// Thread micro-tile: 4 points (p = ty + 32*jp) x 4 codes (c = tx + 8*jc).
// acc packed f32x2 over (even-d, odd-d) partial sums.
// smem: r tile 128 x 33 float4 (pad) + e double buffer 2 x 32 x 33 + sidx.
// ---------------------------------------------------------------------------
#define RPAD 33
#define EBUFO 4224              // 128*33 float4
#define ETILE 1056              // 32*33 float4

__global__ void __launch_bounds__(256, 2)
rvq_layer_kernel(const float* __restrict__ embed_all, int q, float* __restrict__ out)
{
    extern __shared__ float4 sm4[];
    float4* r4s  = sm4;                          // 67,584 B
    float4* ebuf = sm4 + EBUFO;                  // 33,792 B (2 tiles)
    int*    sidx = (int*)(sm4 + EBUFO + 2 * ETILE);  // 512 B

    const int tid = threadIdx.x;
    const int tx  = tid & 7;
    const int ty  = tid >> 3;
    const int blockStart = blockIdx.x * 128;

    const float4* eq = (const float4*)(embed_all + (size_t)q * (K_ * D_));
    float4* rg = (float4*)g_resid;

    // ---- load residual tile: 128 pts x 32 float4, pad-33 rows ----
    #pragma unroll
    for (int i = 0; i < 16; i++) {
        int f  = tid + 256 * i;
        int p  = f >> 5;
        int s0 = f & 31;
        int n  = blockStart + p;
        if (n >= N_) n = 0;
        r4s[p * RPAD + s0] = rg[(size_t)n * 32 + s0];
    }

    // ---- preload e chunk 0 into registers ----
    float4 er[4];
    const int erow = (tid + 0)   >> 5;   // pattern shared by all 4: f>>5 for f=tid+256i
    #pragma unroll
    for (int i = 0; i < 4; i++) {
        int f = tid + 256 * i;
        er[i] = eq[(size_t)((f >> 5)) * 32 + (f & 31)];
    }
    (void)erow;

    float best[4];
    int   bidx[4];
    #pragma unroll
    for (int j = 0; j < 4; j++) { best[j] = -3.4e38f; bidx[j] = 0; }

    for (int c = 0; c < 32; ++c) {
        float4* eb = ebuf + (c & 1) * ETILE;
        // ---- store prefetched e tile (buffer c&1 was last read 2 chunks ago) ----
        #pragma unroll
        for (int i = 0; i < 4; i++) {
            int f = tid + 256 * i;
            eb[(f >> 5) * RPAD + (f & 31)] = er[i];
        }
        // ---- issue LDG for next chunk (consumed next iteration) ----
        if (c < 31) {
            #pragma unroll
            for (int i = 0; i < 4; i++) {
                int f = tid + 256 * i;
                er[i] = eq[(size_t)((c + 1) * 32 + (f >> 5)) * 32 + (f & 31)];
            }
        }
        // ---- code norms for this chunk ----
        float cn[4];
        #pragma unroll
        for (int jc = 0; jc < 4; jc++)
            cn[jc] = g_cnorm[q * K_ + c * 32 + tx + 8 * jc];

        __syncthreads();

        // ---- 128 x 32 x 128d GEMM, f32x2-packed accumulators ----
        unsigned long long acc[4][4];
        #pragma unroll
        for (int a = 0; a < 4; a++)
            #pragma unroll
            for (int b2 = 0; b2 < 4; b2++) acc[a][b2] = 0ULL;

        #pragma unroll 2
        for (int d4 = 0; d4 < 32; ++d4) {
            float4 ra[4], ev[4];
            #pragma unroll
            for (int jp = 0; jp < 4; jp++)
                ra[jp] = r4s[(ty + 32 * jp) * RPAD + d4];
            #pragma unroll
            for (int jc = 0; jc < 4; jc++)
                ev[jc] = eb[(tx + 8 * jc) * RPAD + d4];
            #pragma unroll
            for (int jp = 0; jp < 4; jp++) {
                const unsigned long long r01 = ((const unsigned long long*)&ra[jp])[0];
                const unsigned long long r23 = ((const unsigned long long*)&ra[jp])[1];
                #pragma unroll
                for (int jc = 0; jc < 4; jc++) {
                    ffma2(acc[jp][jc], r01, ((const unsigned long long*)&ev[jc])[0]);
                    ffma2(acc[jp][jc], r23, ((const unsigned long long*)&ev[jc])[1]);
                }
            }
        }

        // ---- epilogue: score = 2*(lo+hi) - |e|^2, running first-max argmax ----
        #pragma unroll
        for (int jp = 0; jp < 4; jp++) {
            #pragma unroll
            for (int jc = 0; jc < 4; jc++) {
                const unsigned long long a = acc[jp][jc];
                const float lo = __uint_as_float((unsigned)(a & 0xffffffffu));
                const float hi = __uint_as_float((unsigned)(a >> 32));
                const float s  = 2.0f * (lo + hi) - cn[jc];
                const int cg   = c * 32 + tx + 8 * jc;
                if (s > best[jp]) { best[jp] = s; bidx[jp] = cg; }
            }
        }
    }

    // ---- reduce argmax across the 8 tx-lanes sharing each point ----
    #pragma unroll
    for (int jp = 0; jp < 4; jp++) {
        float v  = best[jp];
        int   ix = bidx[jp];
        #pragma unroll
        for (int delta = 1; delta < 8; delta <<= 1) {
            float ov = __shfl_xor_sync(0xffffffffu, v, delta);
            int   oi = __shfl_xor_sync(0xffffffffu, ix, delta);
            if (ov > v || (ov == v && oi < ix)) { v = ov; ix = oi; }
        }
        if (tx == 0) sidx[ty + 32 * jp] = ix;
    }
    __syncthreads();

    // ---- write indices as float (output dtype = float32) ----
    if (tid < 128) {
        int n = blockStart + tid;
        if (n < N_) out[(size_t)q * N_ + n] = (float)sidx[tid];
    }

    // ---- residual update: r(smem) - e[best] -> global ----
    #pragma unroll
    for (int i = 0; i < 16; i++) {
        int f  = tid + 256 * i;
        int p  = f >> 5;
        int d4 = f & 31;
        int n  = blockStart + p;
        if (n < N_) {
            float4 r = r4s[p * RPAD + d4];
            float4 e = eq[(size_t)sidx[p] * 32 + d4];
            float4 w;
            w.x = r.x - e.x; w.y = r.y - e.y; w.z = r.z - e.z; w.w = r.w - e.w;
            rg[(size_t)n * 32 + d4] = w;
        }
    }
}

// ---------------------------------------------------------------------------
extern "C" void kernel_launch(void* const* d_in, const int* in_sizes, int n_in,
                              void* d_out, int out_size)
{
    const float* embeddings = (const float*)d_in[0];
    const float* embed      = (const float*)d_in[1];
    if (n_in >= 2 && in_sizes[0] == Q_ * K_ * D_ && in_sizes[1] == B_ * D_ * T_) {
        const float* t = embeddings; embeddings = embed; embed = t;
    }
    float* out = (float*)d_out;

    const int smem_bytes = (EBUFO + 2 * ETILE) * 16 + 512;   // 101,888 + 512
    cudaFuncSetAttribute(rvq_layer_kernel,
                         cudaFuncAttributeMaxDynamicSharedMemorySize, smem_bytes);

    transpose_kernel<<<dim3(71, 4, 32), dim3(32, 8)>>>(embeddings);
    cnorm_kernel<<<4096, 256>>>(embed);
    for (int q = 0; q < Q_; q++) {
        rvq_layer_kernel<<<NBLK, 256, smem_bytes>>>(embed, q, out);
    }
}

// round 6
// speedup vs baseline: 1.0898x; 1.0054x over previous
#include <cuda_runtime.h>
#include <cstdint>

#define B_ 32
#define D_ 128
#define T_ 2250
#define Q_ 32
#define K_ 1024
#define N_ (B_*T_)          // 72000
#define NBLK 563            // ceil(N/128)

// Residual scratch [N][D] and per-code squared norms [Q][K].
__device__ __align__(16) float g_resid[(size_t)N_ * D_];
__device__ __align__(16) float g_cnorm[Q_ * K_];

// ---------------------------------------------------------------------------
__global__ void transpose_kernel(const float* __restrict__ in)
{
    __shared__ float tile[32][33];
    const int b  = blockIdx.z;
    const int t0 = blockIdx.x * 32;
    const int d0 = blockIdx.y * 32;
    const int tx = threadIdx.x;
    const int ty = threadIdx.y;

    #pragma unroll
    for (int k = 0; k < 4; k++) {
        int d = d0 + ty + k * 8;
        int t = t0 + tx;
        float v = 0.0f;
        if (t < T_) v = in[((size_t)b * D_ + d) * T_ + t];
        tile[ty + k * 8][tx] = v;
    }
    __syncthreads();
    #pragma unroll
    for (int k = 0; k < 4; k++) {
        int t = t0 + ty + k * 8;
        int d = d0 + tx;
        if (t < T_) g_resid[((size_t)b * T_ + t) * D_ + d] = tile[tx][ty + k * 8];
    }
}

// ---------------------------------------------------------------------------
__global__ void cnorm_kernel(const float* __restrict__ embed)
{
    const int wid  = threadIdx.x >> 5;
    const int lane = threadIdx.x & 31;
    const int code = blockIdx.x * 8 + wid;
    float s = 0.0f;
    #pragma unroll
    for (int j = 0; j < 4; j++) {
        float v = embed[(size_t)code * D_ + lane + 32 * j];
        s = fmaf(v, v, s);
    }
    #pragma unroll
    for (int d = 16; d; d >>= 1) s += __shfl_xor_sync(0xffffffffu, s, d);
    if (lane == 0) g_cnorm[code] = s;
}

// ---------------------------------------------------------------------------
// Packed dual-FMA: acc.(lo,hi) += a.(lo,hi) * b.(lo,hi)   (sm_100+ f32x2)
__device__ __forceinline__ void ffma2(unsigned long long& acc,
                                      unsigned long long a,
                                      unsigned long long b)
{
    asm("fma.rn.f32x2 %0, %1, %2, %0;" : "+l"(acc) : "l"(a), "l"(b));
}

// ---------------------------------------------------------------------------
// One RVQ layer. Block = 256 threads (tx = tid&15, ty = tid>>4), 128 points.
// K in 8 chunks of 128 codes, full D=128 resident in smem.
// Thread micro-tile: 8 points (p = ty + 16*jp) x 8 codes (c = tx + 16*jc).
// acc packed f32x2 over (even-d, odd-d) partial sums (same order as R5).
// smem: r tile 128 x 33 float4 + e tile 128 x 33 float4 + sidx = 135.7 KB.
// ---------------------------------------------------------------------------
#define RPAD 33
#define RT_F4 (128 * RPAD)      // 4224 float4 per tile

__global__ void __launch_bounds__(256, 1)
rvq_layer_kernel(const float* __restrict__ embed_all, int q, float* __restrict__ out)
{
    extern __shared__ float4 sm4[];
    float4* r4s  = sm4;                       // 67,584 B
    float4* e4s  = sm4 + RT_F4;               // 67,584 B
    int*    sidx = (int*)(sm4 + 2 * RT_F4);   // 512 B

    const int tid = threadIdx.x;
    const int tx  = tid & 15;
    const int ty  = tid >> 4;
    const int blockStart = blockIdx.x * 128;

    const float4* eq = (const float4*)(embed_all + (size_t)q * (K_ * D_));
    float4* rg = (float4*)g_resid;

    // ---- load residual tile: 128 pts x 32 float4 ----
    #pragma unroll
    for (int i = 0; i < 16; i++) {
        int f  = tid + 256 * i;
        int p  = f >> 5;
        int s0 = f & 31;
        int n  = blockStart + p;
        if (n >= N_) n = 0;
        r4s[p * RPAD + s0] = rg[(size_t)n * 32 + s0];
    }

    float best[8];
    int   bidx[8];
    #pragma unroll
    for (int j = 0; j < 8; j++) { best[j] = -3.4e38f; bidx[j] = 0; }

    for (int ch = 0; ch < 8; ++ch) {
        __syncthreads();   // previous chunk's readers done with e4s
        // ---- load e tile: 128 codes x 32 float4 ----
        #pragma unroll
        for (int i = 0; i < 16; i++) {
            int f   = tid + 256 * i;
            int row = f >> 5;
            int s0  = f & 31;
            e4s[row * RPAD + s0] = eq[(size_t)(ch * 128 + row) * 32 + s0];
        }
        // ---- code norms for this chunk ----
        float cn[8];
        #pragma unroll
        for (int jc = 0; jc < 8; jc++)
            cn[jc] = g_cnorm[q * K_ + ch * 128 + tx + 16 * jc];
        __syncthreads();

        // ---- 128 x 128 x 128d GEMM, f32x2-packed accumulators ----
        unsigned long long acc[8][8];
        #pragma unroll
        for (int a = 0; a < 8; a++)
            #pragma unroll
            for (int b2 = 0; b2 < 8; b2++) acc[a][b2] = 0ULL;

        for (int d4 = 0; d4 < 32; ++d4) {
            float4 ev[8];
            #pragma unroll
            for (int jc = 0; jc < 8; jc++)
                ev[jc] = e4s[(tx + 16 * jc) * RPAD + d4];
            #pragma unroll
            for (int jp = 0; jp < 8; jp++) {
                const float4 ra = r4s[(ty + 16 * jp) * RPAD + d4];
                const unsigned long long r01 = ((const unsigned long long*)&ra)[0];
                const unsigned long long r23 = ((const unsigned long long*)&ra)[1];
                #pragma unroll
                for (int jc = 0; jc < 8; jc++)
                    ffma2(acc[jp][jc], r01, ((const unsigned long long*)&ev[jc])[0]);
                #pragma unroll
                for (int jc = 0; jc < 8; jc++)
                    ffma2(acc[jp][jc], r23, ((const unsigned long long*)&ev[jc])[1]);
            }
        }

        // ---- epilogue: score = 2*(lo+hi) - |e|^2, running first-max argmax ----
        #pragma unroll
        for (int jp = 0; jp < 8; jp++) {
            #pragma unroll
            for (int jc = 0; jc < 8; jc++) {
                const unsigned long long a = acc[jp][jc];
                const float lo = __uint_as_float((unsigned)(a & 0xffffffffu));
                const float hi = __uint_as_float((unsigned)(a >> 32));
                const float s  = 2.0f * (lo + hi) - cn[jc];
                const int cg   = ch * 128 + tx + 16 * jc;
                if (s > best[jp]) { best[jp] = s; bidx[jp] = cg; }
            }
        }
    }

    // ---- reduce argmax across the 16 tx-lanes sharing each point ----
    #pragma unroll
    for (int jp = 0; jp < 8; jp++) {
        float v  = best[jp];
        int   ix = bidx[jp];
        #pragma unroll
        for (int delta = 1; delta < 16; delta <<= 1) {
            float ov = __shfl_xor_sync(0xffffffffu, v, delta);
            int   oi = __shfl_xor_sync(0xffffffffu, ix, delta);
            if (ov > v || (ov == v && oi < ix)) { v = ov; ix = oi; }
        }
        if (tx == 0) sidx[ty + 16 * jp] = ix;
    }
    __syncthreads();

    // ---- write indices as float (output dtype = float32) ----
    if (tid < 128) {
        int n = blockStart + tid;
        if (n < N_) out[(size_t)q * N_ + n] = (float)sidx[tid];
    }

    // ---- residual update: r(smem) - e[best] -> global ----
    #pragma unroll
    for (int i = 0; i < 16; i++) {
        int f  = tid + 256 * i;
        int p  = f >> 5;
        int d4 = f & 31;
        int n  = blockStart + p;
        if (n < N_) {
            float4 r = r4s[p * RPAD + d4];
            float4 e = eq[(size_t)sidx[p] * 32 + d4];
            float4 w;
            w.x = r.x - e.x; w.y = r.y - e.y; w.z = r.z - e.z; w.w = r.w - e.w;
            rg[(size_t)n * 32 + d4] = w;
        }
    }
}

// ---------------------------------------------------------------------------
extern "C" void kernel_launch(void* const* d_in, const int* in_sizes, int n_in,
                              void* d_out, int out_size)
{
    const float* embeddings = (const float*)d_in[0];
    const float* embed      = (const float*)d_in[1];
    if (n_in >= 2 && in_sizes[0] == Q_ * K_ * D_ && in_sizes[1] == B_ * D_ * T_) {
        const float* t = embeddings; embeddings = embed; embed = t;
    }
    float* out = (float*)d_out;

    const int smem_bytes = 2 * RT_F4 * 16 + 512;   // 135,680 B
    cudaFuncSetAttribute(rvq_layer_kernel,
                         cudaFuncAttributeMaxDynamicSharedMemorySize, smem_bytes);

    transpose_kernel<<<dim3(71, 4, 32), dim3(32, 8)>>>(embeddings);
    cnorm_kernel<<<4096, 256>>>(embed);
    for (int q = 0; q < Q_; q++) {
        rvq_layer_kernel<<<NBLK, 256, smem_bytes>>>(embed, q, out);
    }
}

// round 7
// speedup vs baseline: 1.2330x; 1.1314x over previous
#include <cuda_runtime.h>
#include <cstdint>

#define B_ 32
#define D_ 128
#define T_ 2250
#define Q_ 32
#define K_ 1024
#define N_ (B_*T_)          // 72000
#define NBLK 563            // ceil(N/128)

// Residual scratch [N][D] and per-code squared norms [Q][K].
__device__ __align__(16) float g_resid[(size_t)N_ * D_];
__device__ __align__(16) float g_cnorm[Q_ * K_];

// ---------------------------------------------------------------------------
__global__ void transpose_kernel(const float* __restrict__ in)
{
    __shared__ float tile[32][33];
    const int b  = blockIdx.z;
    const int t0 = blockIdx.x * 32;
    const int d0 = blockIdx.y * 32;
    const int tx = threadIdx.x;
    const int ty = threadIdx.y;

    #pragma unroll
    for (int k = 0; k < 4; k++) {
        int d = d0 + ty + k * 8;
        int t = t0 + tx;
        float v = 0.0f;
        if (t < T_) v = in[((size_t)b * D_ + d) * T_ + t];
        tile[ty + k * 8][tx] = v;
    }
    __syncthreads();
    #pragma unroll
    for (int k = 0; k < 4; k++) {
        int t = t0 + ty + k * 8;
        int d = d0 + tx;
        if (t < T_) g_resid[((size_t)b * T_ + t) * D_ + d] = tile[tx][ty + k * 8];
    }
}

// ---------------------------------------------------------------------------
__global__ void cnorm_kernel(const float* __restrict__ embed)
{
    const int wid  = threadIdx.x >> 5;
    const int lane = threadIdx.x & 31;
    const int code = blockIdx.x * 8 + wid;
    float s = 0.0f;
    #pragma unroll
    for (int j = 0; j < 4; j++) {
        float v = embed[(size_t)code * D_ + lane + 32 * j];
        s = fmaf(v, v, s);
    }
    #pragma unroll
    for (int d = 16; d; d >>= 1) s += __shfl_xor_sync(0xffffffffu, s, d);
    if (lane == 0) g_cnorm[code] = s;
}

// ---------------------------------------------------------------------------
// Packed dual-FMA: acc.(lo,hi) += a.(lo,hi) * b.(lo,hi)   (sm_100+ f32x2)
__device__ __forceinline__ void ffma2(unsigned long long& acc,
                                      unsigned long long a,
                                      unsigned long long b)
{
    asm("fma.rn.f32x2 %0, %1, %2, %0;" : "+l"(acc) : "l"(a), "l"(b));
}

// ---------------------------------------------------------------------------
// One RVQ layer. Block = 512 threads (tx = tid&15, ty = tid>>4), 128 points.
// K in 8 chunks of 128 codes, full D=128 resident in smem.
// Thread micro-tile: 4 points (p = ty + 32*jp) x 8 codes (c = tx + 16*jc).
// acc packed f32x2 over (even-d, odd-d) partial sums (same order as R5/R6).
// smem: r tile 128 x 33 float4 + e tile 128 x 33 float4 + sidx = 135.7 KB.
// ---------------------------------------------------------------------------
#define RPAD 33
#define RT_F4 (128 * RPAD)      // 4224 float4 per tile

__global__ void __launch_bounds__(512, 1)
rvq_layer_kernel(const float* __restrict__ embed_all, int q, float* __restrict__ out)
{
    extern __shared__ float4 sm4[];
    float4* r4s  = sm4;                       // 67,584 B
    float4* e4s  = sm4 + RT_F4;               // 67,584 B
    int*    sidx = (int*)(sm4 + 2 * RT_F4);   // 512 B

    const int tid = threadIdx.x;
    const int tx  = tid & 15;
    const int ty  = tid >> 4;                 // 0..31
    const int blockStart = blockIdx.x * 128;

    const float4* eq = (const float4*)(embed_all + (size_t)q * (K_ * D_));
    float4* rg = (float4*)g_resid;

    // ---- load residual tile: 128 pts x 32 float4 ----
    #pragma unroll
    for (int i = 0; i < 8; i++) {
        int f  = tid + 512 * i;
        int p  = f >> 5;
        int s0 = f & 31;
        int n  = blockStart + p;
        if (n >= N_) n = 0;
        r4s[p * RPAD + s0] = rg[(size_t)n * 32 + s0];
    }

    float best[4];
    int   bidx[4];
    #pragma unroll
    for (int j = 0; j < 4; j++) { best[j] = -3.4e38f; bidx[j] = 0; }

    for (int ch = 0; ch < 8; ++ch) {
        __syncthreads();   // previous chunk's readers done with e4s
        // ---- load e tile: 128 codes x 32 float4 ----
        #pragma unroll
        for (int i = 0; i < 8; i++) {
            int f   = tid + 512 * i;
            int row = f >> 5;
            int s0  = f & 31;
            e4s[row * RPAD + s0] = eq[(size_t)(ch * 128 + row) * 32 + s0];
        }
        __syncthreads();

        // ---- 128 x 128 x 128d GEMM, f32x2-packed accumulators ----
        unsigned long long acc[4][8];
        #pragma unroll
        for (int a = 0; a < 4; a++)
            #pragma unroll
            for (int b2 = 0; b2 < 8; b2++) acc[a][b2] = 0ULL;

        #pragma unroll 1
        for (int d4 = 0; d4 < 32; ++d4) {
            float4 ev[8];
            #pragma unroll
            for (int jc = 0; jc < 8; jc++)
                ev[jc] = e4s[(tx + 16 * jc) * RPAD + d4];
            #pragma unroll
            for (int jp = 0; jp < 4; jp++) {
                const float4 ra = r4s[(ty + 32 * jp) * RPAD + d4];
                const unsigned long long r01 = ((const unsigned long long*)&ra)[0];
                const unsigned long long r23 = ((const unsigned long long*)&ra)[1];
                #pragma unroll
                for (int jc = 0; jc < 8; jc++)
                    ffma2(acc[jp][jc], r01, ((const unsigned long long*)&ev[jc])[0]);
                #pragma unroll
                for (int jc = 0; jc < 8; jc++)
                    ffma2(acc[jp][jc], r23, ((const unsigned long long*)&ev[jc])[1]);
            }
        }

        // ---- epilogue: score = 2*(lo+hi) - |e|^2, running first-max argmax ----
        #pragma unroll
        for (int jc = 0; jc < 8; jc++) {
            const float cn = g_cnorm[q * K_ + ch * 128 + tx + 16 * jc];
            const int   cg = ch * 128 + tx + 16 * jc;
            #pragma unroll
            for (int jp = 0; jp < 4; jp++) {
                const unsigned long long a = acc[jp][jc];
                const float lo = __uint_as_float((unsigned)(a & 0xffffffffu));
                const float hi = __uint_as_float((unsigned)(a >> 32));
                const float s  = 2.0f * (lo + hi) - cn;
                if (s > best[jp]) { best[jp] = s; bidx[jp] = cg; }
            }
        }
    }

    // ---- reduce argmax across the 16 tx-lanes (half-warp) per point ----
    #pragma unroll
    for (int jp = 0; jp < 4; jp++) {
        float v  = best[jp];
        int   ix = bidx[jp];
        #pragma unroll
        for (int delta = 1; delta < 16; delta <<= 1) {
            float ov = __shfl_xor_sync(0xffffffffu, v, delta);
            int   oi = __shfl_xor_sync(0xffffffffu, ix, delta);
            if (ov > v || (ov == v && oi < ix)) { v = ov; ix = oi; }
        }
        if (tx == 0) sidx[ty + 32 * jp] = ix;
    }
    __syncthreads();

    // ---- write indices as float (output dtype = float32) ----
    if (tid < 128) {
        int n = blockStart + tid;
        if (n < N_) out[(size_t)q * N_ + n] = (float)sidx[tid];
    }

    // ---- residual update: r(smem) - e[best] -> global ----
    #pragma unroll
    for (int i = 0; i < 8; i++) {
        int f  = tid + 512 * i;
        int p  = f >> 5;
        int d4 = f & 31;
        int n  = blockStart + p;
        if (n < N_) {
            float4 r = r4s[p * RPAD + d4];
            float4 e = eq[(size_t)sidx[p] * 32 + d4];
            float4 w;
            w.x = r.x - e.x; w.y = r.y - e.y; w.z = r.z - e.z; w.w = r.w - e.w;
            rg[(size_t)n * 32 + d4] = w;
        }
    }
}

// ---------------------------------------------------------------------------
extern "C" void kernel_launch(void* const* d_in, const int* in_sizes, int n_in,
                              void* d_out, int out_size)
{
    const float* embeddings = (const float*)d_in[0];
    const float* embed      = (const float*)d_in[1];
    if (n_in >= 2 && in_sizes[0] == Q_ * K_ * D_ && in_sizes[1] == B_ * D_ * T_) {
        const float* t = embeddings; embeddings = embed; embed = t;
    }
    float* out = (float*)d_out;

    const int smem_bytes = 2 * RT_F4 * 16 + 512;   // 135,680 B
    cudaFuncSetAttribute(rvq_layer_kernel,
                         cudaFuncAttributeMaxDynamicSharedMemorySize, smem_bytes);

    transpose_kernel<<<dim3(71, 4, 32), dim3(32, 8)>>>(embeddings);
    cnorm_kernel<<<4096, 256>>>(embed);
    for (int q = 0; q < Q_; q++) {
        rvq_layer_kernel<<<NBLK, 512, smem_bytes>>>(embed, q, out);
    }
}